// round 1
// baseline (speedup 1.0000x reference)
#include <cuda_runtime.h>
#include <math.h>
#include <stdint.h>

// ---------------------------------------------------------------------------
// Problem constants (Qwen3.5 GatedDeltaNet): B=2, T=4096, D=2048
// NV=32 value heads, NK=16 key heads, DK=DV=128, conv kernel KC=4
// ---------------------------------------------------------------------------
#define BATCH   2
#define TLEN    4096
#define BT      8192            // BATCH*TLEN tokens
#define DMODEL  2048
#define NVH     32
#define NKH     16
#define DK      128
#define DV      128
#define KEYDIM  (NKH*DK)        // 2048
#define VALDIM  (NVH*DV)        // 4096
#define CONVDIM (2*KEYDIM + VALDIM)  // 8192

// ---------------------------------------------------------------------------
// Scratch (static device globals; no runtime allocation allowed)
// ---------------------------------------------------------------------------
__device__ float g_mixed[(size_t)BT * CONVDIM];   // 256 MB  (pre-conv qkv)
__device__ float g_q[(size_t)BT * KEYDIM];        //  64 MB
__device__ float g_k[(size_t)BT * KEYDIM];        //  64 MB
__device__ float g_v[(size_t)BT * VALDIM];        // 128 MB
__device__ float g_z[(size_t)BT * VALDIM];        // 128 MB
__device__ float g_braw[BT * NVH];
__device__ float g_araw[BT * NVH];
__device__ float g_beta[BT * NVH];
__device__ float g_decay[BT * NVH];
__device__ float g_o[(size_t)BT * VALDIM];        // 128 MB (scan out, gated in-place)

// ---------------------------------------------------------------------------
// Tiled fp32 SGEMM: C[M,N] = A[M,K] @ B[K,N], all row-major.
// 128x128 tile, BK=16, 256 threads, 8x8 per-thread microtile.
// M must be a multiple of 128, K a multiple of 16. N may be arbitrary mult of 4.
// ---------------------------------------------------------------------------
#define GBM 128
#define GBN 128
#define GBK 16

__global__ __launch_bounds__(256) void sgemm_kernel(
    const float* __restrict__ A, const float* __restrict__ B,
    float* __restrict__ C, int M, int N, int K)
{
    __shared__ float As[GBK][GBM];
    __shared__ float Bs[GBK][GBN];

    const int bm = blockIdx.y;
    const int bn = blockIdx.x;
    const int tid = threadIdx.x;

    // A loader: 128 rows x 16 cols = 512 float4, 2 per thread
    const int aRow  = tid >> 2;          // 0..63
    const int aCol4 = (tid & 3) * 4;     // 0,4,8,12
    // B loader: 16 rows x 128 cols = 512 float4, 2 per thread
    const int bRow  = tid >> 5;          // 0..7
    const int bCol4 = (tid & 31) * 4;    // 0..124

    const float* Ab = A + (size_t)bm * GBM * K;

    float acc[8][8];
#pragma unroll
    for (int i = 0; i < 8; i++)
#pragma unroll
        for (int j = 0; j < 8; j++) acc[i][j] = 0.f;

    const int ty = tid >> 4;   // 0..15 -> rows ty*8
    const int tx = tid & 15;   // 0..15 -> cols tx*8

    for (int kt = 0; kt < K; kt += GBK) {
        // load A tile (transposed into As[k][m])
#pragma unroll
        for (int r = 0; r < 2; r++) {
            int row = aRow + r * 64;
            float4 av = *(const float4*)(Ab + (size_t)row * K + kt + aCol4);
            As[aCol4 + 0][row] = av.x;
            As[aCol4 + 1][row] = av.y;
            As[aCol4 + 2][row] = av.z;
            As[aCol4 + 3][row] = av.w;
        }
        // load B tile
#pragma unroll
        for (int r = 0; r < 2; r++) {
            int row = bRow + r * 8;
            int col = bn * GBN + bCol4;
            float4 bv = make_float4(0.f, 0.f, 0.f, 0.f);
            if (col < N)
                bv = *(const float4*)(B + (size_t)(kt + row) * N + col);
            *(float4*)&Bs[row][bCol4] = bv;
        }
        __syncthreads();

#pragma unroll
        for (int k = 0; k < GBK; k++) {
            float ra[8], rb[8];
            const float4* a4 = (const float4*)&As[k][ty * 8];
            const float4* b4 = (const float4*)&Bs[k][tx * 8];
            float4 av0 = a4[0], av1 = a4[1];
            float4 bv0 = b4[0], bv1 = b4[1];
            ra[0]=av0.x; ra[1]=av0.y; ra[2]=av0.z; ra[3]=av0.w;
            ra[4]=av1.x; ra[5]=av1.y; ra[6]=av1.z; ra[7]=av1.w;
            rb[0]=bv0.x; rb[1]=bv0.y; rb[2]=bv0.z; rb[3]=bv0.w;
            rb[4]=bv1.x; rb[5]=bv1.y; rb[6]=bv1.z; rb[7]=bv1.w;
#pragma unroll
            for (int i = 0; i < 8; i++)
#pragma unroll
                for (int j = 0; j < 8; j++)
                    acc[i][j] = fmaf(ra[i], rb[j], acc[i][j]);
        }
        __syncthreads();
    }

    // store
#pragma unroll
    for (int i = 0; i < 8; i++) {
        size_t row = (size_t)(bm * GBM + ty * 8 + i);
#pragma unroll
        for (int j = 0; j < 8; j += 4) {
            int col = bn * GBN + tx * 8 + j;
            if (col < N) {
                float4 cv = make_float4(acc[i][j], acc[i][j+1], acc[i][j+2], acc[i][j+3]);
                *(float4*)(C + row * N + col) = cv;
            }
        }
    }
}

static inline void launch_sgemm(const float* A, const float* B, float* C,
                                int M, int N, int K)
{
    dim3 grid((N + GBN - 1) / GBN, M / GBM);
    sgemm_kernel<<<grid, 256>>>(A, B, C, M, N, K);
}

// ---------------------------------------------------------------------------
// Causal depthwise conv (KC=4) + SiLU + split into q/k/v
// ---------------------------------------------------------------------------
__global__ void conv_silu_split_kernel(const float* __restrict__ mixed,
                                       const float* __restrict__ conv_w,
                                       float* __restrict__ q,
                                       float* __restrict__ k,
                                       float* __restrict__ v)
{
    size_t idx = (size_t)blockIdx.x * blockDim.x + threadIdx.x;
    if (idx >= (size_t)BT * CONVDIM) return;
    int c = (int)(idx & (CONVDIM - 1));
    size_t bt = idx >> 13;                 // / CONVDIM
    int t = (int)(bt & (TLEN - 1));        // position within batch

    float4 w = *(const float4*)(conv_w + (size_t)c * 4);
    const float* base = mixed + c;
    float x0 = (t >= 3) ? base[(bt - 3) * CONVDIM] : 0.f;
    float x1 = (t >= 2) ? base[(bt - 2) * CONVDIM] : 0.f;
    float x2 = (t >= 1) ? base[(bt - 1) * CONVDIM] : 0.f;
    float x3 = base[bt * CONVDIM];

    float acc = x0 * w.x + x1 * w.y + x2 * w.z + x3 * w.w;
    float s = acc / (1.f + expf(-acc));    // silu

    if (c < KEYDIM)           q[bt * KEYDIM + c] = s;
    else if (c < 2 * KEYDIM)  k[bt * KEYDIM + (c - KEYDIM)] = s;
    else                      v[bt * VALDIM + (c - 2 * KEYDIM)] = s;
}

// ---------------------------------------------------------------------------
// L2 norm over DK=128 (one warp per row); q gets extra DK^-0.5
// rows 0..BT*NKH-1 -> q, rows BT*NKH..2*BT*NKH-1 -> k
// ---------------------------------------------------------------------------
__global__ void l2norm_qk_kernel(float* __restrict__ q, float* __restrict__ k)
{
    int wg   = (blockIdx.x * blockDim.x + threadIdx.x) >> 5;
    int lane = threadIdx.x & 31;
    const int nrows = BT * NKH;
    if (wg >= 2 * nrows) return;

    float* base;
    float extra;
    if (wg < nrows) { base = q + (size_t)wg * DK; extra = 0.08838834764831845f; } // 128^-0.5
    else            { base = k + (size_t)(wg - nrows) * DK; extra = 1.f; }

    float4 x = ((float4*)base)[lane];
    float ss = x.x*x.x + x.y*x.y + x.z*x.z + x.w*x.w;
#pragma unroll
    for (int off = 16; off > 0; off >>= 1)
        ss += __shfl_xor_sync(0xffffffffu, ss, off);
    float inv = rsqrtf(ss + 1e-6f) * extra;
    x.x *= inv; x.y *= inv; x.z *= inv; x.w *= inv;
    ((float4*)base)[lane] = x;
}

// ---------------------------------------------------------------------------
// beta = sigmoid(braw); decay = exp(-exp(A_log)*softplus(araw + dt_bias))
// ---------------------------------------------------------------------------
__global__ void beta_decay_kernel(const float* __restrict__ braw,
                                  const float* __restrict__ araw,
                                  const float* __restrict__ dt_bias,
                                  const float* __restrict__ A_log,
                                  float* __restrict__ beta,
                                  float* __restrict__ decay)
{
    int idx = blockIdx.x * blockDim.x + threadIdx.x;
    if (idx >= BT * NVH) return;
    int h = idx & (NVH - 1);
    float b = braw[idx];
    beta[idx] = 1.f / (1.f + expf(-b));
    float a = araw[idx] + dt_bias[h];
    float sp = (a > 20.f) ? a : log1pf(expf(a));
    decay[idx] = expf(-expf(A_log[h]) * sp);
}

// ---------------------------------------------------------------------------
// Gated delta rule scan.
// grid: 128 blocks = (b in 0..1) x (h in 0..31) x (vseg in 0..1)
// 128 threads: thread t -> local col = t>>1 (0..63), half = t&1 (k-range half)
// State S[k=half*64 .. +64][col] lives in 64 registers per thread.
// Pair reduction (kS, o) via shfl_xor lane^1.
// ---------------------------------------------------------------------------
__global__ void __launch_bounds__(128) scan_kernel(
    const float* __restrict__ qn, const float* __restrict__ kn,
    const float* __restrict__ v,  const float* __restrict__ decay,
    const float* __restrict__ beta, float* __restrict__ o)
{
    const int blk = blockIdx.x;
    const int b   = blk >> 6;
    const int rem = blk & 63;
    const int h   = rem >> 1;
    const int seg = rem & 1;
    const int h2  = h >> 1;          // source key head
    const int tid = threadIdx.x;
    const int col  = tid >> 1;       // 0..63
    const int half = tid & 1;
    const int gcol = seg * 64 + col;
    const int koff = half * 64;

    __shared__ float sq[128];
    __shared__ float sk[128];

    float S[64];
#pragma unroll
    for (int i = 0; i < 64; i++) S[i] = 0.f;

    const size_t bt0 = (size_t)b * TLEN;

    // prefetch t = 0
    float pq = qn[((bt0)*NKH + h2) * DK + tid];
    float pk = kn[((bt0)*NKH + h2) * DK + tid];
    float pv = v [((bt0)*NVH + h ) * DV + gcol];
    float pd = decay[bt0 * NVH + h];
    float pb = beta [bt0 * NVH + h];

    for (int t = 0; t < TLEN; t++) {
        __syncthreads();
        sq[tid] = pq;
        sk[tid] = pk;
        float cv = pv, cd = pd, cb = pb;
        __syncthreads();

        if (t + 1 < TLEN) {
            size_t bt = bt0 + t + 1;
            pq = qn[(bt*NKH + h2) * DK + tid];
            pk = kn[(bt*NKH + h2) * DK + tid];
            pv = v [(bt*NVH + h ) * DV + gcol];
            pd = decay[bt * NVH + h];
            pb = beta [bt * NVH + h];
        }

        // decay + k^T S (partial over this thread's 64 k's)
        float a0 = 0.f, a1 = 0.f, a2 = 0.f, a3 = 0.f;
#pragma unroll
        for (int i = 0; i < 64; i += 4) {
            S[i+0] *= cd; a0 = fmaf(sk[koff+i+0], S[i+0], a0);
            S[i+1] *= cd; a1 = fmaf(sk[koff+i+1], S[i+1], a1);
            S[i+2] *= cd; a2 = fmaf(sk[koff+i+2], S[i+2], a2);
            S[i+3] *= cd; a3 = fmaf(sk[koff+i+3], S[i+3], a3);
        }
        float kS = (a0 + a1) + (a2 + a3);
        kS += __shfl_xor_sync(0xffffffffu, kS, 1);

        float upd = cb * (cv - kS);

        // rank-1 update + q^T S
        float o0 = 0.f, o1 = 0.f, o2 = 0.f, o3 = 0.f;
#pragma unroll
        for (int i = 0; i < 64; i += 4) {
            S[i+0] = fmaf(sk[koff+i+0], upd, S[i+0]); o0 = fmaf(sq[koff+i+0], S[i+0], o0);
            S[i+1] = fmaf(sk[koff+i+1], upd, S[i+1]); o1 = fmaf(sq[koff+i+1], S[i+1], o1);
            S[i+2] = fmaf(sk[koff+i+2], upd, S[i+2]); o2 = fmaf(sq[koff+i+2], S[i+2], o2);
            S[i+3] = fmaf(sk[koff+i+3], upd, S[i+3]); o3 = fmaf(sq[koff+i+3], S[i+3], o3);
        }
        float oa = (o0 + o1) + (o2 + o3);
        oa += __shfl_xor_sync(0xffffffffu, oa, 1);
        if (!half)
            o[((bt0 + t)*NVH + h) * DV + gcol] = oa;
    }
}

// ---------------------------------------------------------------------------
// Gated RMSNorm: o = o * rsqrt(mean(o^2)+1e-6) * norm_w * silu(z)
// one warp per (bt, head) row of 128
// ---------------------------------------------------------------------------
__global__ void gate_kernel(float* __restrict__ o, const float* __restrict__ z,
                            const float* __restrict__ norm_w)
{
    int wg   = (blockIdx.x * blockDim.x + threadIdx.x) >> 5;
    int lane = threadIdx.x & 31;
    if (wg >= BT * NVH) return;

    float4* orow = (float4*)(o + (size_t)wg * DV);
    float4 x = orow[lane];
    float ss = x.x*x.x + x.y*x.y + x.z*x.z + x.w*x.w;
#pragma unroll
    for (int off = 16; off > 0; off >>= 1)
        ss += __shfl_xor_sync(0xffffffffu, ss, off);
    float r = rsqrtf(ss * (1.f / DV) + 1e-6f);

    // z layout: [BT, NVH*DV] with head h at cols [h*DV, (h+1)*DV) -> same linear idx
    float4 zv = ((const float4*)(z + (size_t)wg * DV))[lane];
    float4 nw = ((const float4*)norm_w)[lane];

    float s0 = zv.x / (1.f + expf(-zv.x));
    float s1 = zv.y / (1.f + expf(-zv.y));
    float s2 = zv.z / (1.f + expf(-zv.z));
    float s3 = zv.w / (1.f + expf(-zv.w));

    x.x = x.x * r * nw.x * s0;
    x.y = x.y * r * nw.y * s1;
    x.z = x.z * r * nw.z * s2;
    x.w = x.w * r * nw.w * s3;
    orow[lane] = x;
}

// ---------------------------------------------------------------------------
// Launch
// ---------------------------------------------------------------------------
extern "C" void kernel_launch(void* const* d_in, const int* in_sizes, int n_in,
                              void* d_out, int out_size)
{
    const float* hs      = (const float*)d_in[0];  // [B,T,D]
    const float* W_qkv   = (const float*)d_in[1];  // [D, 8192]
    const float* W_z     = (const float*)d_in[2];  // [D, 4096]
    const float* W_b     = (const float*)d_in[3];  // [D, 32]
    const float* W_a     = (const float*)d_in[4];  // [D, 32]
    const float* conv_w  = (const float*)d_in[5];  // [8192, 4]
    const float* dt_bias = (const float*)d_in[6];  // [32]
    const float* A_log   = (const float*)d_in[7];  // [32]
    const float* norm_w  = (const float*)d_in[8];  // [128]
    const float* W_out   = (const float*)d_in[9];  // [4096, 2048]
    float* out = (float*)d_out;                    // [B,T,D]

    float *mixed, *q, *k, *v, *z, *braw, *araw, *beta, *decay, *o;
    cudaGetSymbolAddress((void**)&mixed, g_mixed);
    cudaGetSymbolAddress((void**)&q,     g_q);
    cudaGetSymbolAddress((void**)&k,     g_k);
    cudaGetSymbolAddress((void**)&v,     g_v);
    cudaGetSymbolAddress((void**)&z,     g_z);
    cudaGetSymbolAddress((void**)&braw,  g_braw);
    cudaGetSymbolAddress((void**)&araw,  g_araw);
    cudaGetSymbolAddress((void**)&beta,  g_beta);
    cudaGetSymbolAddress((void**)&decay, g_decay);
    cudaGetSymbolAddress((void**)&o,     g_o);

    // 1) projections
    launch_sgemm(hs, W_qkv, mixed, BT, CONVDIM, DMODEL);
    launch_sgemm(hs, W_z,   z,     BT, VALDIM,  DMODEL);
    launch_sgemm(hs, W_b,   braw,  BT, NVH,     DMODEL);
    launch_sgemm(hs, W_a,   araw,  BT, NVH,     DMODEL);

    // 2) conv + silu + split
    {
        size_t n = (size_t)BT * CONVDIM;
        conv_silu_split_kernel<<<(unsigned)((n + 255) / 256), 256>>>(mixed, conv_w, q, k, v);
    }

    // 3) l2 norm q/k
    {
        int rows = 2 * BT * NKH;          // warps needed
        l2norm_qk_kernel<<<(rows + 7) / 8, 256>>>(q, k);
    }

    // 4) beta/decay
    beta_decay_kernel<<<(BT * NVH + 255) / 256, 256>>>(braw, araw, dt_bias, A_log, beta, decay);

    // 5) gated delta scan
    scan_kernel<<<BATCH * NVH * 2, 128>>>(q, k, v, decay, beta, o);

    // 6) gated rmsnorm
    {
        int rows = BT * NVH;
        gate_kernel<<<(rows + 7) / 8, 256>>>(o, z, norm_w);
    }

    // 7) output projection
    launch_sgemm(o, W_out, out, BT, DMODEL, VALDIM);
}

// round 2
// speedup vs baseline: 2.1061x; 2.1061x over previous
#include <cuda_runtime.h>
#include <math.h>
#include <stdint.h>

// ---------------------------------------------------------------------------
// Problem constants (Qwen3.5 GatedDeltaNet): B=2, T=4096, D=2048
// ---------------------------------------------------------------------------
#define BATCH   2
#define TLEN    4096
#define BT      8192
#define DMODEL  2048
#define NVH     32
#define NKH     16
#define DK      128
#define DV      128
#define KEYDIM  (NKH*DK)                 // 2048
#define VALDIM  (NVH*DV)                 // 4096
#define CONVDIM (2*KEYDIM + VALDIM)      // 8192

// ---------------------------------------------------------------------------
// Scratch (static device globals)
// ---------------------------------------------------------------------------
__device__ float g_mixed[(size_t)BT * CONVDIM];
__device__ float g_q[(size_t)BT * KEYDIM];
__device__ float g_k[(size_t)BT * KEYDIM];
__device__ float g_v[(size_t)BT * VALDIM];
__device__ float g_z[(size_t)BT * VALDIM];
__device__ float g_ba[BT * 64];          // packed [b(32) | a(32)] projections
__device__ float g_wba[DMODEL * 64];     // packed W_b|W_a
__device__ float g_beta[BT * NVH];
__device__ float g_decay[BT * NVH];
__device__ float g_o[(size_t)BT * VALDIM];

// ---------------------------------------------------------------------------
// TF32 tensor-core GEMM: C[M,N] = A[M,K] @ B[K,N], row-major fp32 in/out.
// 128x128 block tile, BK=16, 256 threads (8 warps of 64x32), 3-stage cp.async.
// M % 128 == 0, K % 16 == 0, N % 4 == 0 (zero-filled / guarded beyond N).
// ---------------------------------------------------------------------------
#define TSTAGES 3
#define TBM 128
#define TBN 128
#define TBK 16
#define LDA_S 20            // padded A stride (floats): conflict-free frag loads
#define LDB_S 136           // padded B stride (floats): conflict-free frag loads
#define A_STAGE (TBM*LDA_S) // 2560 floats
#define B_STAGE (TBK*LDB_S) // 2176 floats
#define GEMM_SMEM (TSTAGES*(A_STAGE+B_STAGE)*4)   // 56832 bytes

__device__ __forceinline__ uint32_t f2tf(float x) {
    uint32_t r; asm("cvt.rna.tf32.f32 %0, %1;" : "=r"(r) : "f"(x)); return r;
}

__device__ __forceinline__ void cp16(float* dst, const float* src, bool pred) {
    uint32_t d = (uint32_t)__cvta_generic_to_shared(dst);
    int sz = pred ? 16 : 0;
    asm volatile("cp.async.cg.shared.global [%0], [%1], 16, %2;\n"
                 :: "r"(d), "l"(src), "r"(sz));
}

__device__ __forceinline__ void mma_tf32(float* c, const uint32_t* a, const uint32_t* b) {
    asm volatile(
        "mma.sync.aligned.m16n8k8.row.col.f32.tf32.tf32.f32 "
        "{%0,%1,%2,%3}, {%4,%5,%6,%7}, {%8,%9}, {%0,%1,%2,%3};"
        : "+f"(c[0]), "+f"(c[1]), "+f"(c[2]), "+f"(c[3])
        : "r"(a[0]), "r"(a[1]), "r"(a[2]), "r"(a[3]), "r"(b[0]), "r"(b[1]));
}

__global__ __launch_bounds__(256, 2) void gemm_tf32_kernel(
    const float* __restrict__ A, const float* __restrict__ B,
    float* __restrict__ C, int M, int N, int K)
{
    extern __shared__ float smem[];
    float* As = smem;
    float* Bs = smem + TSTAGES * A_STAGE;

    const int tid  = threadIdx.x;
    const int bm   = blockIdx.y;
    const int bn   = blockIdx.x;
    const int warp = tid >> 5;
    const int lane = tid & 31;
    const int g    = lane >> 2;   // group 0..7
    const int tig  = lane & 3;    // thread in group
    const int wm   = (warp >> 2) * 64;   // warp m-offset (0 or 64)
    const int wn   = (warp & 3) * 32;    // warp n-offset (0,32,64,96)

    float acc[4][4][4];
#pragma unroll
    for (int i = 0; i < 4; i++)
#pragma unroll
        for (int j = 0; j < 4; j++)
#pragma unroll
            for (int r = 0; r < 4; r++) acc[i][j][r] = 0.f;

    const int KT = K / TBK;

    // ---- stage loader ----
    auto load_stage = [&](int s, int kt) {
        float* as = As + s * A_STAGE;
        float* bs = Bs + s * B_STAGE;
#pragma unroll
        for (int h = 0; h < 2; h++) {           // A: 128 rows x 4 float4
            int id  = tid + h * 256;
            int row = id >> 2, c = id & 3;
            const float* src = A + (size_t)(bm * TBM + row) * K + kt * TBK + c * 4;
            cp16(as + row * LDA_S + c * 4, src, true);
        }
#pragma unroll
        for (int h = 0; h < 2; h++) {           // B: 16 rows x 32 float4
            int id  = tid + h * 256;
            int row = id >> 5, c = id & 31;
            int col = bn * TBN + c * 4;
            bool ok = col < N;
            const float* src = B + (size_t)(kt * TBK + row) * N + (ok ? col : 0);
            cp16(bs + row * LDB_S + c * 4, src, ok);
        }
        asm volatile("cp.async.commit_group;");
    };

    load_stage(0, 0);
    load_stage(1, 1);

    for (int kt = 0; kt < KT; kt++) {
        asm volatile("cp.async.wait_group 1;");
        __syncthreads();

        if (kt + 2 < KT) load_stage((kt + 2) % TSTAGES, kt + 2);
        else             asm volatile("cp.async.commit_group;");

        const float* as = As + (kt % TSTAGES) * A_STAGE;
        const float* bs = Bs + (kt % TSTAGES) * B_STAGE;

#pragma unroll
        for (int kk = 0; kk < 2; kk++) {
            const int k0 = kk * 8;
            uint32_t af[4][4], bf[4][2];
#pragma unroll
            for (int i = 0; i < 4; i++) {
                int r0 = wm + 16 * i + g;
                af[i][0] = f2tf(as[(r0    ) * LDA_S + k0 + tig    ]);
                af[i][1] = f2tf(as[(r0 + 8) * LDA_S + k0 + tig    ]);
                af[i][2] = f2tf(as[(r0    ) * LDA_S + k0 + tig + 4]);
                af[i][3] = f2tf(as[(r0 + 8) * LDA_S + k0 + tig + 4]);
            }
#pragma unroll
            for (int j = 0; j < 4; j++) {
                int cn = wn + 8 * j + g;
                bf[j][0] = f2tf(bs[(k0 + tig    ) * LDB_S + cn]);
                bf[j][1] = f2tf(bs[(k0 + tig + 4) * LDB_S + cn]);
            }
#pragma unroll
            for (int i = 0; i < 4; i++)
#pragma unroll
                for (int j = 0; j < 4; j++)
                    mma_tf32(acc[i][j], af[i], bf[j]);
        }
    }

    // ---- epilogue ----
#pragma unroll
    for (int i = 0; i < 4; i++) {
        int r0 = bm * TBM + wm + 16 * i + g;
#pragma unroll
        for (int j = 0; j < 4; j++) {
            int cn = bn * TBN + wn + 8 * j + 2 * tig;
            if (cn < N) {
                float2 v0 = make_float2(acc[i][j][0], acc[i][j][1]);
                float2 v1 = make_float2(acc[i][j][2], acc[i][j][3]);
                *(float2*)(C + (size_t)r0 * N + cn)       = v0;
                *(float2*)(C + (size_t)(r0 + 8) * N + cn) = v1;
            }
        }
    }
}

static inline void launch_gemm(const float* A, const float* B, float* C,
                               int M, int N, int K)
{
    dim3 grid((N + TBN - 1) / TBN, M / TBM);
    gemm_tf32_kernel<<<grid, 256, GEMM_SMEM>>>(A, B, C, M, N, K);
}

// ---------------------------------------------------------------------------
// Pack W_b|W_a into [DMODEL, 64]
// ---------------------------------------------------------------------------
__global__ void pack_wba_kernel(const float* __restrict__ Wb,
                                const float* __restrict__ Wa,
                                float* __restrict__ Wba)
{
    int idx = blockIdx.x * blockDim.x + threadIdx.x;
    if (idx >= DMODEL * 64) return;
    int k = idx >> 6, j = idx & 63;
    Wba[idx] = (j < 32) ? Wb[k * 32 + j] : Wa[k * 32 + (j - 32)];
}

// ---------------------------------------------------------------------------
// Causal depthwise conv (KC=4) + SiLU + split into q/k/v
// ---------------------------------------------------------------------------
__global__ void conv_silu_split_kernel(const float* __restrict__ mixed,
                                       const float* __restrict__ conv_w,
                                       float* __restrict__ q,
                                       float* __restrict__ k,
                                       float* __restrict__ v)
{
    size_t idx = (size_t)blockIdx.x * blockDim.x + threadIdx.x;
    if (idx >= (size_t)BT * CONVDIM) return;
    int c = (int)(idx & (CONVDIM - 1));
    size_t bt = idx >> 13;
    int t = (int)(bt & (TLEN - 1));

    float4 w = *(const float4*)(conv_w + (size_t)c * 4);
    const float* base = mixed + c;
    float x0 = (t >= 3) ? base[(bt - 3) * CONVDIM] : 0.f;
    float x1 = (t >= 2) ? base[(bt - 2) * CONVDIM] : 0.f;
    float x2 = (t >= 1) ? base[(bt - 1) * CONVDIM] : 0.f;
    float x3 = base[bt * CONVDIM];

    float acc = x0 * w.x + x1 * w.y + x2 * w.z + x3 * w.w;
    float s = acc / (1.f + expf(-acc));

    if (c < KEYDIM)           q[bt * KEYDIM + c] = s;
    else if (c < 2 * KEYDIM)  k[bt * KEYDIM + (c - KEYDIM)] = s;
    else                      v[bt * VALDIM + (c - 2 * KEYDIM)] = s;
}

// ---------------------------------------------------------------------------
// L2 norm over DK=128 (one warp per row); q gets extra DK^-0.5
// ---------------------------------------------------------------------------
__global__ void l2norm_qk_kernel(float* __restrict__ q, float* __restrict__ k)
{
    int wg   = (blockIdx.x * blockDim.x + threadIdx.x) >> 5;
    int lane = threadIdx.x & 31;
    const int nrows = BT * NKH;
    if (wg >= 2 * nrows) return;

    float* base;
    float extra;
    if (wg < nrows) { base = q + (size_t)wg * DK; extra = 0.08838834764831845f; }
    else            { base = k + (size_t)(wg - nrows) * DK; extra = 1.f; }

    float4 x = ((float4*)base)[lane];
    float ss = x.x*x.x + x.y*x.y + x.z*x.z + x.w*x.w;
#pragma unroll
    for (int off = 16; off > 0; off >>= 1)
        ss += __shfl_xor_sync(0xffffffffu, ss, off);
    float inv = rsqrtf(ss + 1e-6f) * extra;
    x.x *= inv; x.y *= inv; x.z *= inv; x.w *= inv;
    ((float4*)base)[lane] = x;
}

// ---------------------------------------------------------------------------
// beta = sigmoid(b); decay = exp(-exp(A_log)*softplus(a + dt_bias))
// reads packed ba: [BT][64], cols 0-31 = b, 32-63 = a
// ---------------------------------------------------------------------------
__global__ void beta_decay_kernel(const float* __restrict__ ba,
                                  const float* __restrict__ dt_bias,
                                  const float* __restrict__ A_log,
                                  float* __restrict__ beta,
                                  float* __restrict__ decay)
{
    int idx = blockIdx.x * blockDim.x + threadIdx.x;
    if (idx >= BT * NVH) return;
    int h = idx & (NVH - 1);
    int bt = idx >> 5;
    float b = ba[bt * 64 + h];
    beta[idx] = 1.f / (1.f + expf(-b));
    float a = ba[bt * 64 + 32 + h] + dt_bias[h];
    float sp = (a > 20.f) ? a : log1pf(expf(a));
    decay[idx] = expf(-expf(A_log[h]) * sp);
}

// ---------------------------------------------------------------------------
// Gated delta rule scan (register-resident state, 128 blocks x 128 threads)
// ---------------------------------------------------------------------------
__global__ void __launch_bounds__(128) scan_kernel(
    const float* __restrict__ qn, const float* __restrict__ kn,
    const float* __restrict__ v,  const float* __restrict__ decay,
    const float* __restrict__ beta, float* __restrict__ o)
{
    const int blk = blockIdx.x;
    const int b   = blk >> 6;
    const int rem = blk & 63;
    const int h   = rem >> 1;
    const int seg = rem & 1;
    const int h2  = h >> 1;
    const int tid = threadIdx.x;
    const int col  = tid >> 1;
    const int half = tid & 1;
    const int gcol = seg * 64 + col;
    const int koff = half * 64;

    __shared__ float sq[128];
    __shared__ float sk[128];

    float S[64];
#pragma unroll
    for (int i = 0; i < 64; i++) S[i] = 0.f;

    const size_t bt0 = (size_t)b * TLEN;

    float pq = qn[((bt0)*NKH + h2) * DK + tid];
    float pk = kn[((bt0)*NKH + h2) * DK + tid];
    float pv = v [((bt0)*NVH + h ) * DV + gcol];
    float pd = decay[bt0 * NVH + h];
    float pb = beta [bt0 * NVH + h];

    for (int t = 0; t < TLEN; t++) {
        __syncthreads();
        sq[tid] = pq;
        sk[tid] = pk;
        float cv = pv, cd = pd, cb = pb;
        __syncthreads();

        if (t + 1 < TLEN) {
            size_t bt = bt0 + t + 1;
            pq = qn[(bt*NKH + h2) * DK + tid];
            pk = kn[(bt*NKH + h2) * DK + tid];
            pv = v [(bt*NVH + h ) * DV + gcol];
            pd = decay[bt * NVH + h];
            pb = beta [bt * NVH + h];
        }

        float a0 = 0.f, a1 = 0.f, a2 = 0.f, a3 = 0.f;
#pragma unroll
        for (int i = 0; i < 64; i += 4) {
            S[i+0] *= cd; a0 = fmaf(sk[koff+i+0], S[i+0], a0);
            S[i+1] *= cd; a1 = fmaf(sk[koff+i+1], S[i+1], a1);
            S[i+2] *= cd; a2 = fmaf(sk[koff+i+2], S[i+2], a2);
            S[i+3] *= cd; a3 = fmaf(sk[koff+i+3], S[i+3], a3);
        }
        float kS = (a0 + a1) + (a2 + a3);
        kS += __shfl_xor_sync(0xffffffffu, kS, 1);

        float upd = cb * (cv - kS);

        float o0 = 0.f, o1 = 0.f, o2 = 0.f, o3 = 0.f;
#pragma unroll
        for (int i = 0; i < 64; i += 4) {
            S[i+0] = fmaf(sk[koff+i+0], upd, S[i+0]); o0 = fmaf(sq[koff+i+0], S[i+0], o0);
            S[i+1] = fmaf(sk[koff+i+1], upd, S[i+1]); o1 = fmaf(sq[koff+i+1], S[i+1], o1);
            S[i+2] = fmaf(sk[koff+i+2], upd, S[i+2]); o2 = fmaf(sq[koff+i+2], S[i+2], o2);
            S[i+3] = fmaf(sk[koff+i+3], upd, S[i+3]); o3 = fmaf(sq[koff+i+3], S[i+3], o3);
        }
        float oa = (o0 + o1) + (o2 + o3);
        oa += __shfl_xor_sync(0xffffffffu, oa, 1);
        if (!half)
            o[((bt0 + t)*NVH + h) * DV + gcol] = oa;
    }
}

// ---------------------------------------------------------------------------
// Gated RMSNorm
// ---------------------------------------------------------------------------
__global__ void gate_kernel(float* __restrict__ o, const float* __restrict__ z,
                            const float* __restrict__ norm_w)
{
    int wg   = (blockIdx.x * blockDim.x + threadIdx.x) >> 5;
    int lane = threadIdx.x & 31;
    if (wg >= BT * NVH) return;

    float4* orow = (float4*)(o + (size_t)wg * DV);
    float4 x = orow[lane];
    float ss = x.x*x.x + x.y*x.y + x.z*x.z + x.w*x.w;
#pragma unroll
    for (int off = 16; off > 0; off >>= 1)
        ss += __shfl_xor_sync(0xffffffffu, ss, off);
    float r = rsqrtf(ss * (1.f / DV) + 1e-6f);

    float4 zv = ((const float4*)(z + (size_t)wg * DV))[lane];
    float4 nw = ((const float4*)norm_w)[lane];

    float s0 = zv.x / (1.f + expf(-zv.x));
    float s1 = zv.y / (1.f + expf(-zv.y));
    float s2 = zv.z / (1.f + expf(-zv.z));
    float s3 = zv.w / (1.f + expf(-zv.w));

    x.x = x.x * r * nw.x * s0;
    x.y = x.y * r * nw.y * s1;
    x.z = x.z * r * nw.z * s2;
    x.w = x.w * r * nw.w * s3;
    orow[lane] = x;
}

// ---------------------------------------------------------------------------
// Launch
// ---------------------------------------------------------------------------
extern "C" void kernel_launch(void* const* d_in, const int* in_sizes, int n_in,
                              void* d_out, int out_size)
{
    const float* hs      = (const float*)d_in[0];
    const float* W_qkv   = (const float*)d_in[1];
    const float* W_z     = (const float*)d_in[2];
    const float* W_b     = (const float*)d_in[3];
    const float* W_a     = (const float*)d_in[4];
    const float* conv_w  = (const float*)d_in[5];
    const float* dt_bias = (const float*)d_in[6];
    const float* A_log   = (const float*)d_in[7];
    const float* norm_w  = (const float*)d_in[8];
    const float* W_out   = (const float*)d_in[9];
    float* out = (float*)d_out;

    float *mixed, *q, *k, *v, *z, *ba, *wba, *beta, *decay, *o;
    cudaGetSymbolAddress((void**)&mixed, g_mixed);
    cudaGetSymbolAddress((void**)&q,     g_q);
    cudaGetSymbolAddress((void**)&k,     g_k);
    cudaGetSymbolAddress((void**)&v,     g_v);
    cudaGetSymbolAddress((void**)&z,     g_z);
    cudaGetSymbolAddress((void**)&ba,    g_ba);
    cudaGetSymbolAddress((void**)&wba,   g_wba);
    cudaGetSymbolAddress((void**)&beta,  g_beta);
    cudaGetSymbolAddress((void**)&decay, g_decay);
    cudaGetSymbolAddress((void**)&o,     g_o);

    static bool attr_done = false;
    if (!attr_done) {
        cudaFuncSetAttribute(gemm_tf32_kernel,
                             cudaFuncAttributeMaxDynamicSharedMemorySize, GEMM_SMEM);
        attr_done = true;
    }

    // 0) pack W_b|W_a
    pack_wba_kernel<<<(DMODEL * 64 + 255) / 256, 256>>>(W_b, W_a, wba);

    // 1) projections (tensor cores, tf32)
    launch_gemm(hs, W_qkv, mixed, BT, CONVDIM, DMODEL);
    launch_gemm(hs, W_z,   z,     BT, VALDIM,  DMODEL);
    launch_gemm(hs, wba,   ba,    BT, 64,      DMODEL);

    // 2) conv + silu + split
    {
        size_t n = (size_t)BT * CONVDIM;
        conv_silu_split_kernel<<<(unsigned)((n + 255) / 256), 256>>>(mixed, conv_w, q, k, v);
    }

    // 3) l2 norm q/k
    {
        int rows = 2 * BT * NKH;
        l2norm_qk_kernel<<<(rows + 7) / 8, 256>>>(q, k);
    }

    // 4) beta/decay
    beta_decay_kernel<<<(BT * NVH + 255) / 256, 256>>>(ba, dt_bias, A_log, beta, decay);

    // 5) gated delta scan
    scan_kernel<<<BATCH * NVH * 2, 128>>>(q, k, v, decay, beta, o);

    // 6) gated rmsnorm
    {
        int rows = BT * NVH;
        gate_kernel<<<(rows + 7) / 8, 256>>>(o, z, norm_w);
    }

    // 7) output projection
    launch_gemm(o, W_out, out, BT, DMODEL, VALDIM);
}